// round 1
// baseline (speedup 1.0000x reference)
#include <cuda_runtime.h>
#include <cstdint>

#define N_MAX 50000
#define E_MAX 800000
#define C 64
#define FIN 128
#define D 192
#define NEG_SLOPE 0.2f

// ---------------- scratch (static __device__; no allocations allowed) -------
__device__ __align__(16) float g_hz[N_MAX * C];
__device__ __align__(16) float g_hr[N_MAX * C];
__device__ __align__(16) float g_hh[N_MAX * C];
__device__ __align__(16) float g_acc_z[N_MAX * C];
__device__ __align__(16) float g_acc_r[N_MAX * C];
__device__ __align__(16) float g_acc_h[N_MAX * C];
__device__ __align__(16) float g_Z[N_MAX * C];
__device__ __align__(16) float g_HR[N_MAX * C];
__device__ float g_als_z[N_MAX], g_ald_z[N_MAX];
__device__ float g_als_r[N_MAX], g_ald_r[N_MAX];
__device__ float g_als_h[N_MAX], g_ald_h[N_MAX];
__device__ float g_den_z[N_MAX], g_den_r[N_MAX], g_den_h[N_MAX];

// ---------------- helpers ----------------
__device__ __forceinline__ float lrelu(float x) { return x > 0.f ? x : NEG_SLOPE * x; }

__device__ __forceinline__ void red_add_f32(float* p, float v) {
    asm volatile("red.global.add.f32 [%0], %1;" :: "l"(p), "f"(v) : "memory");
}
__device__ __forceinline__ void red_add_v4(float* p, float4 v) {
    asm volatile("red.global.add.v4.f32 [%0], {%1,%2,%3,%4};"
                 :: "l"(p), "f"(v.x), "f"(v.y), "f"(v.z), "f"(v.w) : "memory");
}

// ---------------- GEMM: O = [A1 | A2] (n x 192) @ B (192 x 64) per gate ------
// BN=128: two gates fused (B1=Wz, B2=Wr) -> g_hz, g_hr
// BN=64 : one gate (B1=Wh)               -> g_hh   (A2in==nullptr => use g_HR)
template <int BN>
__global__ void gemm_kernel(const float* __restrict__ A1, const float* __restrict__ A2in,
                            const float* __restrict__ B1, const float* __restrict__ B2,
                            int which, int n)
{
    constexpr int TN = BN / 16;           // 8 or 4 cols per thread
    __shared__ float As[16 * 64];         // [k][m]
    __shared__ float Bs[16 * BN];         // [k][n]

    const float* A2 = A2in ? A2in : g_HR;
    float* O1 = (which == 0) ? g_hz : g_hh;
    float* O2 = g_hr;

    int tid = threadIdx.x;
    int row0 = blockIdx.x * 64;
    int tr = tid >> 4;                    // 0..15  (4 rows each)
    int tc = tid & 15;                    // 0..15  (TN cols each half)

    float acc[4][TN];
#pragma unroll
    for (int i = 0; i < 4; i++)
#pragma unroll
        for (int j = 0; j < TN; j++) acc[i][j] = 0.f;

    int ar = tid >> 2;                    // 0..63 row in tile
    int akg = tid & 3;                    // k group of 4

    for (int k0 = 0; k0 < D; k0 += 16) {
        // --- load A tile (64 x 16), transposed into As[k][m] ---
        {
            int row = row0 + ar;
            int k = k0 + akg * 4;
            float4 v = make_float4(0.f, 0.f, 0.f, 0.f);
            if (row < n) {
                if (k < FIN) v = *(const float4*)(A1 + (size_t)row * FIN + k);
                else         v = *(const float4*)(A2 + (size_t)row * C + (k - FIN));
            }
            As[(akg * 4 + 0) * 64 + ar] = v.x;
            As[(akg * 4 + 1) * 64 + ar] = v.y;
            As[(akg * 4 + 2) * 64 + ar] = v.z;
            As[(akg * 4 + 3) * 64 + ar] = v.w;
        }
        // --- load B tile (16 x BN) ---
        {
            constexpr int PER = BN / 16;  // floats per thread (8 or 4)
            int i = tid * PER;
            int kk = i / BN;
            int col = i % BN;
            const float* B;
            int bcol;
            if (BN == 128) { B = (col < 64) ? B1 : B2; bcol = col & 63; }
            else           { B = B1; bcol = col; }
            float4 v0 = *(const float4*)(B + (size_t)(k0 + kk) * 64 + bcol);
            *(float4*)(Bs + i) = v0;
            if (BN == 128) {
                float4 v1 = *(const float4*)(B + (size_t)(k0 + kk) * 64 + bcol + 4);
                *(float4*)(Bs + i + 4) = v1;
            }
        }
        __syncthreads();
#pragma unroll
        for (int kk = 0; kk < 16; kk++) {
            float4 a = *(const float4*)(As + kk * 64 + tr * 4);
            float av[4] = {a.x, a.y, a.z, a.w};
            float4 b0 = *(const float4*)(Bs + kk * BN + tc * 4);
            float bv[8];
            bv[0] = b0.x; bv[1] = b0.y; bv[2] = b0.z; bv[3] = b0.w;
            if (BN == 128) {
                float4 b1 = *(const float4*)(Bs + kk * BN + 64 + tc * 4);
                bv[4] = b1.x; bv[5] = b1.y; bv[6] = b1.z; bv[7] = b1.w;
            }
#pragma unroll
            for (int i = 0; i < 4; i++)
#pragma unroll
                for (int j = 0; j < TN; j++) acc[i][j] += av[i] * bv[j];
        }
        __syncthreads();
    }
    // --- store ---
#pragma unroll
    for (int i = 0; i < 4; i++) {
        int row = row0 + tr * 4 + i;
        if (row >= n) continue;
        float4 v0 = make_float4(acc[i][0], acc[i][1], acc[i][2], acc[i][3]);
        *(float4*)(O1 + (size_t)row * 64 + tc * 4) = v0;
        if (BN == 128) {
            float4 v1 = make_float4(acc[i][4], acc[i][5], acc[i][6], acc[i][7]);
            *(float4*)(O2 + (size_t)row * 64 + tc * 4) = v1;
        }
    }
}

// ---------------- per-node: attention scalars + self-loop init of acc/den ---
__global__ void node_attn_init(const float* __restrict__ a_src,
                               const float* __restrict__ a_dst,
                               int gate, int n)
{
    int w = (blockIdx.x * blockDim.x + threadIdx.x) >> 5;
    if (w >= n) return;
    int lane = threadIdx.x & 31;
    const float* h = gate == 0 ? g_hz : gate == 1 ? g_hr : g_hh;
    float* als = gate == 0 ? g_als_z : gate == 1 ? g_als_r : g_als_h;
    float* ald = gate == 0 ? g_ald_z : gate == 1 ? g_ald_r : g_ald_h;
    float* acc = gate == 0 ? g_acc_z : gate == 1 ? g_acc_r : g_acc_h;
    float* den = gate == 0 ? g_den_z : gate == 1 ? g_den_r : g_den_h;

    float h0 = h[(size_t)w * 64 + lane];
    float h1 = h[(size_t)w * 64 + 32 + lane];
    float s = h0 * __ldg(a_src + lane) + h1 * __ldg(a_src + 32 + lane);
    float d = h0 * __ldg(a_dst + lane) + h1 * __ldg(a_dst + 32 + lane);
#pragma unroll
    for (int o = 16; o; o >>= 1) {
        s += __shfl_xor_sync(0xffffffffu, s, o);
        d += __shfl_xor_sync(0xffffffffu, d, o);
    }
    float e = expf(lrelu(s + d));          // self-loop term (src==dst==w)
    acc[(size_t)w * 64 + lane]      = h0 * e;
    acc[(size_t)w * 64 + 32 + lane] = h1 * e;
    if (lane == 0) { als[w] = s; ald[w] = d; den[w] = e; }
}

// ---------------- edge pass for z & r fused: warp/edge, half-warp/gate ------
__global__ void edge_pass_zr(const int* __restrict__ src, const int* __restrict__ dst, int E)
{
    int w = (blockIdx.x * blockDim.x + threadIdx.x) >> 5;
    if (w >= E) return;
    int lane = threadIdx.x & 31;
    int s = __ldg(src + w), d = __ldg(dst + w);
    bool rr = lane >= 16;
    int l = lane & 15;
    const float* als = rr ? g_als_r : g_als_z;
    const float* ald = rr ? g_ald_r : g_ald_z;
    const float* h   = rr ? g_hr : g_hz;
    float* acc = rr ? g_acc_r : g_acc_z;
    float* den = rr ? g_den_r : g_den_z;

    float e = expf(lrelu(__ldg(als + s) + __ldg(ald + d)));
    float4 v = *(const float4*)(h + (size_t)s * 64 + l * 4);
    v.x *= e; v.y *= e; v.z *= e; v.w *= e;
    red_add_v4(acc + (size_t)d * 64 + l * 4, v);
    if (l == 0) red_add_f32(den + d, e);
}

// ---------------- edge pass for h gate: half-warp per edge ------------------
__global__ void edge_pass_h(const int* __restrict__ src, const int* __restrict__ dst, int E)
{
    int hw = (blockIdx.x * blockDim.x + threadIdx.x) >> 4;
    if (hw >= E) return;
    int l = threadIdx.x & 15;
    int s = __ldg(src + hw), d = __ldg(dst + hw);
    float e = expf(lrelu(__ldg(g_als_h + s) + __ldg(g_ald_h + d)));
    float4 v = *(const float4*)(g_hh + (size_t)s * 64 + l * 4);
    v.x *= e; v.y *= e; v.z *= e; v.w *= e;
    red_add_v4(g_acc_h + (size_t)d * 64 + l * 4, v);
    if (l == 0) red_add_f32(g_den_h + d, e);
}

// ---------------- Z/R gates: normalize, sigmoid, build HR -------------------
__global__ void gate_combine(const float* __restrict__ H,
                             const float* __restrict__ bz, const float* __restrict__ br, int n)
{
    int i = blockIdx.x * blockDim.x + threadIdx.x;
    if (i >= n * 64) return;
    int node = i >> 6, c = i & 63;
    float Z = g_acc_z[i] / (g_den_z[node] + 1e-16f) + __ldg(bz + c);
    Z = 1.f / (1.f + expf(-Z));
    float R = g_acc_r[i] / (g_den_r[node] + 1e-16f) + __ldg(br + c);
    R = 1.f / (1.f + expf(-R));
    g_Z[i] = Z;
    g_HR[i] = __ldg(H + i) * R;
}

// ---------------- final: H_tilde + GRU combine ------------------------------
__global__ void final_combine(const float* __restrict__ H, const float* __restrict__ bh,
                              float* __restrict__ out, int n)
{
    int i = blockIdx.x * blockDim.x + threadIdx.x;
    if (i >= n * 64) return;
    int node = i >> 6, c = i & 63;
    float ht = tanhf(g_acc_h[i] / (g_den_h[node] + 1e-16f) + __ldg(bh + c));
    float Z = g_Z[i];
    out[i] = Z * __ldg(H + i) + (1.f - Z) * ht;
}

// ---------------- launch ----------------
extern "C" void kernel_launch(void* const* d_in, const int* in_sizes, int n_in,
                              void* d_out, int out_size)
{
    const float* X    = (const float*)d_in[0];
    const int*   ei   = (const int*)  d_in[1];
    const float* H    = (const float*)d_in[2];
    const float* Wz   = (const float*)d_in[3];
    const float* az_s = (const float*)d_in[4];
    const float* az_d = (const float*)d_in[5];
    const float* bz   = (const float*)d_in[6];
    const float* Wr   = (const float*)d_in[7];
    const float* ar_s = (const float*)d_in[8];
    const float* ar_d = (const float*)d_in[9];
    const float* br   = (const float*)d_in[10];
    const float* Wh   = (const float*)d_in[11];
    const float* ah_s = (const float*)d_in[12];
    const float* ah_d = (const float*)d_in[13];
    const float* bh   = (const float*)d_in[14];

    int n = in_sizes[0] / FIN;
    int E = in_sizes[1] / 2;
    const int* src = ei;
    const int* dst = ei + E;

    int gemm_blocks = (n + 63) / 64;
    int node_blocks = (n * 32 + 255) / 256;
    int elem_blocks = (n * 64 + 255) / 256;

    // --- Z and R gates ---
    gemm_kernel<128><<<gemm_blocks, 256>>>(X, H, Wz, Wr, 0, n);
    node_attn_init<<<node_blocks, 256>>>(az_s, az_d, 0, n);
    node_attn_init<<<node_blocks, 256>>>(ar_s, ar_d, 1, n);
    edge_pass_zr<<<(E * 32 + 255) / 256, 256>>>(src, dst, E);
    gate_combine<<<elem_blocks, 256>>>(H, bz, br, n);

    // --- H_tilde gate ---
    gemm_kernel<64><<<gemm_blocks, 256>>>(X, nullptr, Wh, nullptr, 1, n);
    node_attn_init<<<node_blocks, 256>>>(ah_s, ah_d, 2, n);
    edge_pass_h<<<(E * 16 + 255) / 256, 256>>>(src, dst, E);
    final_combine<<<elem_blocks, 256>>>(H, bh, (float*)d_out, n);
}

// round 6
// speedup vs baseline: 1.1661x; 1.1661x over previous
#include <cuda_runtime.h>
#include <cstdint>

#define N_MAX 50000
#define E_MAX 800000
#define C 64
#define FIN 128
#define D 192
#define NEG_SLOPE 0.2f
#define SCAN_B 512

// ---------------- scratch (static __device__; no allocations allowed) -------
__device__ __align__(16) float g_hzr[N_MAX * 128];   // interleaved z/r: [z2p,z2p+1,r2p,r2p+1]
__device__ __align__(16) float g_hh[N_MAX * C];
__device__ __align__(16) float g_Z[N_MAX * C];
__device__ __align__(16) float g_HR[N_MAX * C];
__device__ float g_als_z[N_MAX], g_ald_z[N_MAX];
__device__ float g_als_r[N_MAX], g_ald_r[N_MAX];
__device__ float g_als_h[N_MAX], g_ald_h[N_MAX];
__device__ int g_cnt[N_MAX];
__device__ int g_rs[N_MAX + 1];     // CSR row starts (by dst)
__device__ int g_cur[N_MAX];        // scatter cursors
__device__ int g_bsum[512], g_boff[512];
__device__ int g_csrc[E_MAX];       // src node per CSR slot

// ---------------- helpers ----------------
__device__ __forceinline__ float lrelu(float x) { return x > 0.f ? x : NEG_SLOPE * x; }
__device__ __forceinline__ float sigmoidf_(float x) { return 1.f / (1.f + __expf(-x)); }

// ================= CSR build =================
__global__ void k_zero_cnt(int n) {
    int i = blockIdx.x * blockDim.x + threadIdx.x;
    if (i < n) g_cnt[i] = 0;
}
__global__ void k_count(const int* __restrict__ dst, int E) {
    int e = blockIdx.x * blockDim.x + threadIdx.x;
    if (e < E) atomicAdd(&g_cnt[dst[e]], 1);
}
__global__ void k_scan1(int n) {   // block-chunk reduce -> g_bsum
    __shared__ int sm[SCAN_B];
    int i = blockIdx.x * SCAN_B + threadIdx.x;
    int c = (i < n) ? g_cnt[i] : 0;
    sm[threadIdx.x] = c;
    __syncthreads();
    for (int off = SCAN_B / 2; off; off >>= 1) {
        if (threadIdx.x < off) sm[threadIdx.x] += sm[threadIdx.x + off];
        __syncthreads();
    }
    if (threadIdx.x == 0) g_bsum[blockIdx.x] = sm[0];
}
__global__ void k_scan2(int nb, int n) {  // serial scan of block sums
    if (threadIdx.x == 0) {
        int run = 0;
        for (int b = 0; b < nb; b++) { g_boff[b] = run; run += g_bsum[b]; }
        g_rs[n] = run;
    }
}
__global__ void k_scan3(int n) {   // per-chunk exclusive scan + offset
    __shared__ int sm[SCAN_B];
    int t = threadIdx.x;
    int i = blockIdx.x * SCAN_B + t;
    int c = (i < n) ? g_cnt[i] : 0;
    sm[t] = c;
    __syncthreads();
    for (int off = 1; off < SCAN_B; off <<= 1) {
        int v = (t >= off) ? sm[t - off] : 0;
        __syncthreads();
        sm[t] += v;
        __syncthreads();
    }
    if (i < n) {
        int excl = g_boff[blockIdx.x] + sm[t] - c;
        g_rs[i] = excl;
        g_cur[i] = excl;
    }
}
__global__ void k_scatter(const int* __restrict__ src, const int* __restrict__ dst, int E) {
    int e = blockIdx.x * blockDim.x + threadIdx.x;
    if (e < E) {
        int pos = atomicAdd(&g_cur[dst[e]], 1);
        g_csrc[pos] = src[e];
    }
}

// ================= GEMMs (Round-1 proven structure) =================
// O = [A1 | A2] (n x 192) @ B (192 x 64).
// gemm_zr: two gates fused (Wz,Wr), interleaved output g_hzr.
__global__ void gemm_zr(const float* __restrict__ A1, const float* __restrict__ A2,
                        const float* __restrict__ B1, const float* __restrict__ B2, int n)
{
    __shared__ float As[16 * 64];
    __shared__ float Bs[16 * 128];

    int tid = threadIdx.x;
    int row0 = blockIdx.x * 64;
    int tr = tid >> 4;
    int tc = tid & 15;

    float acc[4][8];
#pragma unroll
    for (int i = 0; i < 4; i++)
#pragma unroll
        for (int j = 0; j < 8; j++) acc[i][j] = 0.f;

    int ar = tid >> 2;
    int akg = tid & 3;

    for (int k0 = 0; k0 < D; k0 += 16) {
        {
            int row = row0 + ar;
            int k = k0 + akg * 4;
            float4 v = make_float4(0.f, 0.f, 0.f, 0.f);
            if (row < n) {
                if (k < FIN) v = *(const float4*)(A1 + (size_t)row * FIN + k);
                else         v = *(const float4*)(A2 + (size_t)row * C + (k - FIN));
            }
            As[(akg * 4 + 0) * 64 + ar] = v.x;
            As[(akg * 4 + 1) * 64 + ar] = v.y;
            As[(akg * 4 + 2) * 64 + ar] = v.z;
            As[(akg * 4 + 3) * 64 + ar] = v.w;
        }
        {
            int i = tid * 8;
            int kk = i / 128;
            int col = i % 128;
            const float* B = (col < 64) ? B1 : B2;
            int bcol = col & 63;
            float4 v0 = *(const float4*)(B + (size_t)(k0 + kk) * 64 + bcol);
            *(float4*)(Bs + i) = v0;
            float4 v1 = *(const float4*)(B + (size_t)(k0 + kk) * 64 + bcol + 4);
            *(float4*)(Bs + i + 4) = v1;
        }
        __syncthreads();
#pragma unroll
        for (int kk = 0; kk < 16; kk++) {
            float4 a = *(const float4*)(As + kk * 64 + tr * 4);
            float av[4] = {a.x, a.y, a.z, a.w};
            float4 b0 = *(const float4*)(Bs + kk * 128 + tc * 4);
            float4 b1 = *(const float4*)(Bs + kk * 128 + 64 + tc * 4);
            float bv[8] = {b0.x, b0.y, b0.z, b0.w, b1.x, b1.y, b1.z, b1.w};
#pragma unroll
            for (int i = 0; i < 4; i++)
#pragma unroll
                for (int j = 0; j < 8; j++) acc[i][j] += av[i] * bv[j];
        }
        __syncthreads();
    }
    // interleaved store: pairs (z2p,z2p+1,r2p,r2p+1) at offset 4p; thread's z/r cols tc*4..+3
#pragma unroll
    for (int i = 0; i < 4; i++) {
        int row = row0 + tr * 4 + i;
        if (row >= n) continue;
        float* o = g_hzr + (size_t)row * 128 + tc * 8;
        *(float4*)(o)     = make_float4(acc[i][0], acc[i][1], acc[i][4], acc[i][5]);
        *(float4*)(o + 4) = make_float4(acc[i][2], acc[i][3], acc[i][6], acc[i][7]);
    }
}

// gemm_h: single gate, plain output g_hh, A2 = g_HR.
__global__ void gemm_h(const float* __restrict__ A1, const float* __restrict__ B1, int n)
{
    __shared__ float As[16 * 64];
    __shared__ float Bs[16 * 64];

    const float* A2 = g_HR;
    int tid = threadIdx.x;
    int row0 = blockIdx.x * 64;
    int tr = tid >> 4;
    int tc = tid & 15;

    float acc[4][4];
#pragma unroll
    for (int i = 0; i < 4; i++)
#pragma unroll
        for (int j = 0; j < 4; j++) acc[i][j] = 0.f;

    int ar = tid >> 2;
    int akg = tid & 3;

    for (int k0 = 0; k0 < D; k0 += 16) {
        {
            int row = row0 + ar;
            int k = k0 + akg * 4;
            float4 v = make_float4(0.f, 0.f, 0.f, 0.f);
            if (row < n) {
                if (k < FIN) v = *(const float4*)(A1 + (size_t)row * FIN + k);
                else         v = *(const float4*)(A2 + (size_t)row * C + (k - FIN));
            }
            As[(akg * 4 + 0) * 64 + ar] = v.x;
            As[(akg * 4 + 1) * 64 + ar] = v.y;
            As[(akg * 4 + 2) * 64 + ar] = v.z;
            As[(akg * 4 + 3) * 64 + ar] = v.w;
        }
        {
            int i = tid * 4;
            int kk = i / 64;
            int col = i % 64;
            float4 v0 = *(const float4*)(B1 + (size_t)(k0 + kk) * 64 + col);
            *(float4*)(Bs + i) = v0;
        }
        __syncthreads();
#pragma unroll
        for (int kk = 0; kk < 16; kk++) {
            float4 a = *(const float4*)(As + kk * 64 + tr * 4);
            float av[4] = {a.x, a.y, a.z, a.w};
            float4 b0 = *(const float4*)(Bs + kk * 64 + tc * 4);
            float bv[4] = {b0.x, b0.y, b0.z, b0.w};
#pragma unroll
            for (int i = 0; i < 4; i++)
#pragma unroll
                for (int j = 0; j < 4; j++) acc[i][j] += av[i] * bv[j];
        }
        __syncthreads();
    }
#pragma unroll
    for (int i = 0; i < 4; i++) {
        int row = row0 + tr * 4 + i;
        if (row >= n) continue;
        *(float4*)(g_hh + (size_t)row * C + tc * 4) =
            make_float4(acc[i][0], acc[i][1], acc[i][2], acc[i][3]);
    }
}

// ================= attention scalars =================
// z & r fused from interleaved layout. warp per node.
__global__ void node_attn_zr(const float* __restrict__ az_s, const float* __restrict__ az_d,
                             const float* __restrict__ ar_s, const float* __restrict__ ar_d,
                             int n)
{
    int w = (blockIdx.x * blockDim.x + threadIdx.x) >> 5;
    if (w >= n) return;
    int l = threadIdx.x & 31;
    float4 v = *(const float4*)(g_hzr + (size_t)w * 128 + 4 * l);
    float c0s = __ldg(az_s + 2 * l), c1s = __ldg(az_s + 2 * l + 1);
    float c0d = __ldg(az_d + 2 * l), c1d = __ldg(az_d + 2 * l + 1);
    float r0s = __ldg(ar_s + 2 * l), r1s = __ldg(ar_s + 2 * l + 1);
    float r0d = __ldg(ar_d + 2 * l), r1d = __ldg(ar_d + 2 * l + 1);
    float sz = v.x * c0s + v.y * c1s;
    float dz = v.x * c0d + v.y * c1d;
    float sr = v.z * r0s + v.w * r1s;
    float dr = v.z * r0d + v.w * r1d;
#pragma unroll
    for (int o = 16; o; o >>= 1) {
        sz += __shfl_xor_sync(0xffffffffu, sz, o);
        dz += __shfl_xor_sync(0xffffffffu, dz, o);
        sr += __shfl_xor_sync(0xffffffffu, sr, o);
        dr += __shfl_xor_sync(0xffffffffu, dr, o);
    }
    if (l == 0) { g_als_z[w] = sz; g_ald_z[w] = dz; g_als_r[w] = sr; g_ald_r[w] = dr; }
}

__global__ void node_attn_h(const float* __restrict__ a_src, const float* __restrict__ a_dst, int n)
{
    int w = (blockIdx.x * blockDim.x + threadIdx.x) >> 5;
    if (w >= n) return;
    int l = threadIdx.x & 31;
    float h0 = g_hh[(size_t)w * C + l];
    float h1 = g_hh[(size_t)w * C + 32 + l];
    float s = h0 * __ldg(a_src + l) + h1 * __ldg(a_src + 32 + l);
    float d = h0 * __ldg(a_dst + l) + h1 * __ldg(a_dst + 32 + l);
#pragma unroll
    for (int o = 16; o; o >>= 1) {
        s += __shfl_xor_sync(0xffffffffu, s, o);
        d += __shfl_xor_sync(0xffffffffu, d, o);
    }
    if (l == 0) { g_als_h[w] = s; g_ald_h[w] = d; }
}

// ================= fused per-dst accumulation =================
// z & r gates: warp per dst node, register accumulators, no atomics.
// Produces g_Z and g_HR directly (normalize + sigmoid fused).
__global__ void zr_node(const float* __restrict__ H,
                        const float* __restrict__ bz, const float* __restrict__ br, int n)
{
    int d = (blockIdx.x * blockDim.x + threadIdx.x) >> 5;
    if (d >= n) return;
    int l = threadIdx.x & 31;

    float aldz = g_ald_z[d], aldr = g_ald_r[d];
    float alsz = g_als_z[d], alsr = g_als_r[d];

    float ez = 0.f, er = 0.f;
    if (l == 0)  ez = __expf(lrelu(alsz + aldz));
    if (l == 16) er = __expf(lrelu(alsr + aldr));
    ez = __shfl_sync(0xffffffffu, ez, 0);
    er = __shfl_sync(0xffffffffu, er, 16);

    float4 v = *(const float4*)(g_hzr + (size_t)d * 128 + 4 * l);
    float az0 = v.x * ez, az1 = v.y * ez;
    float ar0 = v.z * er, ar1 = v.w * er;
    float denz = ez, denr = er;

    int b = g_rs[d], e_end = g_rs[d + 1];
    int s_next = (b < e_end) ? g_csrc[b] : 0;
    for (int i = b; i < e_end; i++) {
        int s = s_next;
        if (i + 1 < e_end) s_next = g_csrc[i + 1];
        float ez2 = 0.f, er2 = 0.f;
        if (l == 0)  ez2 = __expf(lrelu(g_als_z[s] + aldz));
        if (l == 16) er2 = __expf(lrelu(g_als_r[s] + aldr));
        ez2 = __shfl_sync(0xffffffffu, ez2, 0);
        er2 = __shfl_sync(0xffffffffu, er2, 16);
        float4 u = *(const float4*)(g_hzr + (size_t)s * 128 + 4 * l);
        az0 += u.x * ez2; az1 += u.y * ez2;
        ar0 += u.z * er2; ar1 += u.w * er2;
        denz += ez2; denr += er2;
    }

    float iz = 1.f / (denz + 1e-16f), ir = 1.f / (denr + 1e-16f);
    float Z0 = sigmoidf_(az0 * iz + __ldg(bz + 2 * l));
    float Z1 = sigmoidf_(az1 * iz + __ldg(bz + 2 * l + 1));
    float R0 = sigmoidf_(ar0 * ir + __ldg(br + 2 * l));
    float R1 = sigmoidf_(ar1 * ir + __ldg(br + 2 * l + 1));
    float2 Hv = *(const float2*)(H + (size_t)d * C + 2 * l);
    *(float2*)(g_Z  + (size_t)d * C + 2 * l) = make_float2(Z0, Z1);
    *(float2*)(g_HR + (size_t)d * C + 2 * l) = make_float2(Hv.x * R0, Hv.y * R1);
}

// h gate: warp per dst node; tanh + GRU combine fused; writes final output.
__global__ void h_node(const float* __restrict__ H, const float* __restrict__ bh,
                       float* __restrict__ out, int n)
{
    int d = (blockIdx.x * blockDim.x + threadIdx.x) >> 5;
    if (d >= n) return;
    int l = threadIdx.x & 31;

    float aldh = g_ald_h[d];
    float alsh = g_als_h[d];

    float eh = 0.f;
    if (l == 0) eh = __expf(lrelu(alsh + aldh));
    eh = __shfl_sync(0xffffffffu, eh, 0);

    float2 v = *(const float2*)(g_hh + (size_t)d * C + 2 * l);
    float a0 = v.x * eh, a1 = v.y * eh;
    float den = eh;

    int b = g_rs[d], e_end = g_rs[d + 1];
    int s_next = (b < e_end) ? g_csrc[b] : 0;
    for (int i = b; i < e_end; i++) {
        int s = s_next;
        if (i + 1 < e_end) s_next = g_csrc[i + 1];
        float eh2 = 0.f;
        if (l == 0) eh2 = __expf(lrelu(g_als_h[s] + aldh));
        eh2 = __shfl_sync(0xffffffffu, eh2, 0);
        float2 u = *(const float2*)(g_hh + (size_t)s * C + 2 * l);
        a0 += u.x * eh2; a1 += u.y * eh2;
        den += eh2;
    }

    float inv = 1.f / (den + 1e-16f);
    float ht0 = tanhf(a0 * inv + __ldg(bh + 2 * l));
    float ht1 = tanhf(a1 * inv + __ldg(bh + 2 * l + 1));
    float2 Zv = *(const float2*)(g_Z + (size_t)d * C + 2 * l);
    float2 Hv = *(const float2*)(H + (size_t)d * C + 2 * l);
    float o0 = Zv.x * Hv.x + (1.f - Zv.x) * ht0;
    float o1 = Zv.y * Hv.y + (1.f - Zv.y) * ht1;
    *(float2*)(out + (size_t)d * C + 2 * l) = make_float2(o0, o1);
}

// ---------------- launch ----------------
extern "C" void kernel_launch(void* const* d_in, const int* in_sizes, int n_in,
                              void* d_out, int out_size)
{
    const float* X    = (const float*)d_in[0];
    const int*   ei   = (const int*)  d_in[1];
    const float* H    = (const float*)d_in[2];
    const float* Wz   = (const float*)d_in[3];
    const float* az_s = (const float*)d_in[4];
    const float* az_d = (const float*)d_in[5];
    const float* bz   = (const float*)d_in[6];
    const float* Wr   = (const float*)d_in[7];
    const float* ar_s = (const float*)d_in[8];
    const float* ar_d = (const float*)d_in[9];
    const float* br   = (const float*)d_in[10];
    const float* Wh   = (const float*)d_in[11];
    const float* ah_s = (const float*)d_in[12];
    const float* ah_d = (const float*)d_in[13];
    const float* bh   = (const float*)d_in[14];

    int n = in_sizes[0] / FIN;
    int E = in_sizes[1] / 2;
    const int* src = ei;
    const int* dst = ei + E;

    int nb = (n + SCAN_B - 1) / SCAN_B;
    int gemm_blocks = (n + 63) / 64;
    int warp_blocks = (n * 32 + 255) / 256;
    int eth = (E + 255) / 256;

    // --- CSR build (by dst), shared by all gates ---
    k_zero_cnt<<<(n + 255) / 256, 256>>>(n);
    k_count<<<eth, 256>>>(dst, E);
    k_scan1<<<nb, SCAN_B>>>(n);
    k_scan2<<<1, 32>>>(nb, n);
    k_scan3<<<nb, SCAN_B>>>(n);
    k_scatter<<<eth, 256>>>(src, dst, E);

    // --- Z and R gates ---
    gemm_zr<<<gemm_blocks, 256>>>(X, H, Wz, Wr, n);
    node_attn_zr<<<warp_blocks, 256>>>(az_s, az_d, ar_s, ar_d, n);
    zr_node<<<warp_blocks, 256>>>(H, bz, br, n);

    // --- H_tilde gate ---
    gemm_h<<<gemm_blocks, 256>>>(X, Wh, n);
    node_attn_h<<<warp_blocks, 256>>>(ah_s, ah_d, n);
    h_node<<<warp_blocks, 256>>>(H, bh, (float*)d_out, n);
}